// round 14
// baseline (speedup 1.0000x reference)
#include <cuda_runtime.h>
#include <cuda_bf16.h>
#include <cstdint>
#include <cstddef>

#define D_MODEL 512
#define S_LEN   512
#define BATCH   64
#define NHEAD   8
#define DH      64
#define ROWS    (S_LEN * BATCH)          // 32768
#define NELEM   ((size_t)ROWS * D_MODEL) // 16,777,216
#define WELEM   (D_MODEL * D_MODEL)      // 262,144

// ---------------- scratch (no allocations allowed) ----------------
__device__ float g_xn[NELEM];
__device__ float g_q [NELEM];
__device__ float g_k [NELEM];
__device__ float g_v [NELEM];
__device__ float g_att[NELEM];
__device__ float g_xt[NELEM];
__device__ float g_h1[NELEM];
__device__ float g_wqkv[3 * WELEM];
__device__ float g_w1[WELEM];
__device__ float g_w2[WELEM];

// ================= tf32 warp-mma helpers =================
__device__ __forceinline__ uint32_t f2tf32(float f) {
    uint32_t u;
    asm("cvt.rna.tf32.f32 %0, %1;" : "=r"(u) : "f"(f));
    return u;
}
__device__ __forceinline__ float tf32f(float f) {
    return __uint_as_float(f2tf32(f));
}
__device__ __forceinline__ void mma_tf32(float* c, const uint32_t* a, uint32_t b0, uint32_t b1) {
    asm volatile(
        "mma.sync.aligned.m16n8k8.row.col.f32.tf32.tf32.f32 "
        "{%0,%1,%2,%3}, {%4,%5,%6,%7}, {%8,%9}, {%0,%1,%2,%3};"
        : "+f"(c[0]), "+f"(c[1]), "+f"(c[2]), "+f"(c[3])
        : "r"(a[0]), "r"(a[1]), "r"(a[2]), "r"(a[3]), "r"(b0), "r"(b1));
}
__device__ __forceinline__ void ldsm_x4(uint32_t& r0, uint32_t& r1, uint32_t& r2, uint32_t& r3,
                                        uint32_t addr) {
    asm volatile("ldmatrix.sync.aligned.m8n8.x4.shared.b16 {%0,%1,%2,%3}, [%4];"
                 : "=r"(r0), "=r"(r1), "=r"(r2), "=r"(r3) : "r"(addr));
}
__device__ __forceinline__ uint32_t smem_u32(const void* p) {
    uint32_t a;
    asm("{ .reg .u64 t; cvta.to.shared.u64 t, %1; cvt.u32.u64 %0, t; }" : "=r"(a) : "l"(p));
    return a;
}
__device__ __forceinline__ void cp_async16(uint32_t saddr, const void* g) {
    asm volatile("cp.async.cg.shared.global [%0], [%1], 16;" :: "r"(saddr), "l"(g));
}
#define CP_COMMIT() asm volatile("cp.async.commit_group;" ::: "memory")
#define CP_WAIT0()  asm volatile("cp.async.wait_group 0;" ::: "memory")

// ---------------- fused weight pre-rounding to tf32 (rna) ----------------
__global__ void __launch_bounds__(256) round_w_all(
    const float* __restrict__ Wq, const float* __restrict__ Wk, const float* __restrict__ Wv,
    const float* __restrict__ W1, const float* __restrict__ W2,
    float* __restrict__ wqkv, float* __restrict__ w1, float* __restrict__ w2)
{
    int slot = blockIdx.x * 256 + threadIdx.x;
    int region = slot / (WELEM / 4);
    int off    = slot % (WELEM / 4);
    const float* src;
    float* dst;
    switch (region) {
        case 0: src = Wq; dst = wqkv;              break;
        case 1: src = Wk; dst = wqkv + WELEM;      break;
        case 2: src = Wv; dst = wqkv + 2 * WELEM;  break;
        case 3: src = W1; dst = w1;                break;
        default: src = W2; dst = w2;               break;
    }
    float4 f = ((const float4*)src)[off];
    float4 r = { tf32f(f.x), tf32f(f.y), tf32f(f.z), tf32f(f.w) };
    ((float4*)dst)[off] = r;
}

// ---------------- LayerNorm (optionally fused residual add), tf32-rounded output ----------------
__global__ void __launch_bounds__(128) ln_kernel(
    const float* __restrict__ x, const float* __restrict__ res,
    const float* __restrict__ gamma, const float* __restrict__ beta,
    float* __restrict__ out)
{
    int row = blockIdx.x;
    int t = threadIdx.x;
    const float4* xr = (const float4*)(x + (size_t)row * D_MODEL);
    float4 v = xr[t];
    if (res) {
        const float4* rr = (const float4*)(res + (size_t)row * D_MODEL);
        float4 r = rr[t];
        v.x += r.x; v.y += r.y; v.z += r.z; v.w += r.w;
    }
    float s  = v.x + v.y + v.z + v.w;
    float sq = v.x*v.x + v.y*v.y + v.z*v.z + v.w*v.w;
    #pragma unroll
    for (int o = 16; o > 0; o >>= 1) {
        s  += __shfl_xor_sync(0xffffffffu, s,  o);
        sq += __shfl_xor_sync(0xffffffffu, sq, o);
    }
    __shared__ float ss[4], ssq[4];
    int w = t >> 5;
    if ((t & 31) == 0) { ss[w] = s; ssq[w] = sq; }
    __syncthreads();
    s  = ss[0] + ss[1] + ss[2] + ss[3];
    sq = ssq[0] + ssq[1] + ssq[2] + ssq[3];
    const float invD = 1.0f / D_MODEL;
    float mu   = s * invD;
    float var  = sq * invD - mu * mu;
    float rstd = rsqrtf(var + 1e-5f);
    float4 g = ((const float4*)gamma)[t];
    float4 b = ((const float4*)beta )[t];
    float4 o;
    o.x = tf32f((v.x - mu) * rstd * g.x + b.x);
    o.y = tf32f((v.y - mu) * rstd * g.y + b.y);
    o.z = tf32f((v.z - mu) * rstd * g.z + b.z);
    o.w = tf32f((v.w - mu) * rstd * g.w + b.w);
    ((float4*)(out + (size_t)row * D_MODEL))[t] = o;
}

// ============ shared GEMM config ============
#define GEMM_LDS   36
#define GEMM_STAGE (128 * GEMM_LDS)
#define GEMM_SMEM  (4 * GEMM_STAGE * 4)   // 73728 B

// ============ tf32 GEMM: C = A*W^T (+bias)(+relu)(+res), N=512 ============
template<int MODE>
__global__ void __launch_bounds__(256) tc_gemm(
    const float* __restrict__ A, const float* __restrict__ W,
    const float* __restrict__ bias, const float* __restrict__ res,
    float* __restrict__ C)
{
    constexpr int K = 512, N = 512, BK = 32, LDS = GEMM_LDS;
    extern __shared__ uint32_t dyn[];

    int tid  = threadIdx.x;
    int wid  = tid >> 5, lane = tid & 31;
    int grp  = lane >> 2, tig = lane & 3;
    int m0 = blockIdx.y * 128, n0 = blockIdx.x * 128;
    int wm = wid & 3;
    int wn = wid >> 2;

    int lrow[4], lcol[4];
    #pragma unroll
    for (int it = 0; it < 4; it++) {
        int slot = tid + it * 256;
        lrow[it] = slot >> 3;
        lcol[it] = (slot & 7) * 4;
    }
    uint32_t sA_u[2] = { smem_u32(dyn),                  smem_u32(dyn + GEMM_STAGE)     };
    uint32_t sB_u[2] = { smem_u32(dyn + 2 * GEMM_STAGE), smem_u32(dyn + 3 * GEMM_STAGE) };

    const uint32_t offA = (uint32_t)(((lane & 15) * LDS + ((lane >> 2) & 4)) * 4);
    const uint32_t offB = (uint32_t)((((lane & 7) + ((lane >> 1) & 8)) * LDS + ((lane >> 1) & 4)) * 4);

    float acc[2][8][4];
    #pragma unroll
    for (int i = 0; i < 2; i++)
        #pragma unroll
        for (int j = 0; j < 8; j++)
            #pragma unroll
            for (int q = 0; q < 4; q++) acc[i][j][q] = 0.0f;

    #pragma unroll
    for (int it = 0; it < 4; it++) {
        cp_async16(sA_u[0] + (lrow[it] * LDS + lcol[it]) * 4,
                   A + (size_t)(m0 + lrow[it]) * K + lcol[it]);
        cp_async16(sB_u[0] + (lrow[it] * LDS + lcol[it]) * 4,
                   W + (size_t)(n0 + lrow[it]) * K + lcol[it]);
    }
    CP_COMMIT();

    for (int chunk = 0; chunk < 16; chunk++) {
        int buf = chunk & 1;
        CP_WAIT0();
        __syncthreads();

        if (chunk < 15) {
            int k0 = (chunk + 1) * BK;
            int nbuf = buf ^ 1;
            #pragma unroll
            for (int it = 0; it < 4; it++) {
                cp_async16(sA_u[nbuf] + (lrow[it] * LDS + lcol[it]) * 4,
                           A + (size_t)(m0 + lrow[it]) * K + k0 + lcol[it]);
                cp_async16(sB_u[nbuf] + (lrow[it] * LDS + lcol[it]) * 4,
                           W + (size_t)(n0 + lrow[it]) * K + k0 + lcol[it]);
            }
            CP_COMMIT();
        }

        uint32_t aU = sA_u[buf] + offA;
        uint32_t bU = sB_u[buf] + offB;
        #pragma unroll
        for (int ks = 0; ks < 4; ks++) {
            int kk = ks * 8;
            uint32_t a[2][4];
            #pragma unroll
            for (int mi = 0; mi < 2; mi++)
                ldsm_x4(a[mi][0], a[mi][1], a[mi][2], a[mi][3],
                        aU + (uint32_t)(((wm * 32 + mi * 16) * LDS + kk) * 4));
            uint32_t b[8][2];
            #pragma unroll
            for (int j = 0; j < 4; j++)
                ldsm_x4(b[2*j][0], b[2*j][1], b[2*j+1][0], b[2*j+1][1],
                        bU + (uint32_t)(((wn * 64 + j * 16) * LDS + kk) * 4));
            #pragma unroll
            for (int mi = 0; mi < 2; mi++)
                #pragma unroll
                for (int ni = 0; ni < 8; ni++)
                    mma_tf32(acc[mi][ni], a[mi], b[ni][0], b[ni][1]);
        }
    }

    #pragma unroll
    for (int mi = 0; mi < 2; mi++) {
        #pragma unroll
        for (int h = 0; h < 2; h++) {
            int m = m0 + wm * 32 + mi * 16 + grp + h * 8;
            #pragma unroll
            for (int ni = 0; ni < 8; ni++) {
                int n = n0 + wn * 64 + ni * 8 + tig * 2;
                float2 o;
                o.x = acc[mi][ni][h * 2 + 0];
                o.y = acc[mi][ni][h * 2 + 1];
                if (MODE >= 1) {
                    float2 bb = *(const float2*)(bias + n);
                    o.x += bb.x; o.y += bb.y;
                }
                if (MODE == 1) {
                    o.x = fmaxf(o.x, 0.f); o.y = fmaxf(o.y, 0.f);
                }
                if (MODE == 2) {
                    float2 rr = *(const float2*)(res + (size_t)m * N + n);
                    o.x += rr.x; o.y += rr.y;
                }
                if (MODE != 2) { o.x = tf32f(o.x); o.y = tf32f(o.y); }
                *(float2*)(C + (size_t)m * N + n) = o;
            }
        }
    }
}

// ============ fused QKV GEMM: N=1536 (Wq|Wk|Wv stacked) ============
__global__ void __launch_bounds__(256) tc_gemm_qkv(
    const float* __restrict__ A, const float* __restrict__ W,
    float* __restrict__ Cq, float* __restrict__ Ck, float* __restrict__ Cv)
{
    constexpr int K = 512, LDS = GEMM_LDS, BK = 32;
    extern __shared__ uint32_t dyn[];

    int tid  = threadIdx.x;
    int wid  = tid >> 5, lane = tid & 31;
    int grp  = lane >> 2, tig = lane & 3;
    int m0 = blockIdx.y * 128, n0 = blockIdx.x * 128;
    int wm = wid & 3;
    int wn = wid >> 2;

    int lrow[4], lcol[4];
    #pragma unroll
    for (int it = 0; it < 4; it++) {
        int slot = tid + it * 256;
        lrow[it] = slot >> 3;
        lcol[it] = (slot & 7) * 4;
    }
    uint32_t sA_u[2] = { smem_u32(dyn),                  smem_u32(dyn + GEMM_STAGE)     };
    uint32_t sB_u[2] = { smem_u32(dyn + 2 * GEMM_STAGE), smem_u32(dyn + 3 * GEMM_STAGE) };

    const uint32_t offA = (uint32_t)(((lane & 15) * LDS + ((lane >> 2) & 4)) * 4);
    const uint32_t offB = (uint32_t)((((lane & 7) + ((lane >> 1) & 8)) * LDS + ((lane >> 1) & 4)) * 4);

    float acc[2][8][4];
    #pragma unroll
    for (int i = 0; i < 2; i++)
        #pragma unroll
        for (int j = 0; j < 8; j++)
            #pragma unroll
            for (int q = 0; q < 4; q++) acc[i][j][q] = 0.0f;

    #pragma unroll
    for (int it = 0; it < 4; it++) {
        cp_async16(sA_u[0] + (lrow[it] * LDS + lcol[it]) * 4,
                   A + (size_t)(m0 + lrow[it]) * K + lcol[it]);
        cp_async16(sB_u[0] + (lrow[it] * LDS + lcol[it]) * 4,
                   W + (size_t)(n0 + lrow[it]) * K + lcol[it]);
    }
    CP_COMMIT();

    for (int chunk = 0; chunk < 16; chunk++) {
        int buf = chunk & 1;
        CP_WAIT0();
        __syncthreads();

        if (chunk < 15) {
            int k0 = (chunk + 1) * BK;
            int nbuf = buf ^ 1;
            #pragma unroll
            for (int it = 0; it < 4; it++) {
                cp_async16(sA_u[nbuf] + (lrow[it] * LDS + lcol[it]) * 4,
                           A + (size_t)(m0 + lrow[it]) * K + k0 + lcol[it]);
                cp_async16(sB_u[nbuf] + (lrow[it] * LDS + lcol[it]) * 4,
                           W + (size_t)(n0 + lrow[it]) * K + k0 + lcol[it]);
            }
            CP_COMMIT();
        }

        uint32_t aU = sA_u[buf] + offA;
        uint32_t bU = sB_u[buf] + offB;
        #pragma unroll
        for (int ks = 0; ks < 4; ks++) {
            int kk = ks * 8;
            uint32_t a[2][4];
            #pragma unroll
            for (int mi = 0; mi < 2; mi++)
                ldsm_x4(a[mi][0], a[mi][1], a[mi][2], a[mi][3],
                        aU + (uint32_t)(((wm * 32 + mi * 16) * LDS + kk) * 4));
            uint32_t b[8][2];
            #pragma unroll
            for (int j = 0; j < 4; j++)
                ldsm_x4(b[2*j][0], b[2*j][1], b[2*j+1][0], b[2*j+1][1],
                        bU + (uint32_t)(((wn * 64 + j * 16) * LDS + kk) * 4));
            #pragma unroll
            for (int mi = 0; mi < 2; mi++)
                #pragma unroll
                for (int ni = 0; ni < 8; ni++)
                    mma_tf32(acc[mi][ni], a[mi], b[ni][0], b[ni][1]);
        }
    }

    float* C = (n0 < 512) ? Cq : (n0 < 1024 ? Ck : Cv);
    int nb = n0 & 511;
    #pragma unroll
    for (int mi = 0; mi < 2; mi++) {
        #pragma unroll
        for (int h = 0; h < 2; h++) {
            int m = m0 + wm * 32 + mi * 16 + grp + h * 8;
            #pragma unroll
            for (int ni = 0; ni < 8; ni++) {
                int n = nb + wn * 64 + ni * 8 + tig * 2;
                float2 o;
                o.x = tf32f(acc[mi][ni][h * 2 + 0]);
                o.y = tf32f(acc[mi][ni][h * 2 + 1]);
                *(float2*)(C + (size_t)m * 512 + n) = o;
            }
        }
    }
}

// ============ tf32 tensor-core flash attention (inputs already tf32) ============
__global__ void __launch_bounds__(256, 2) attn_tc_kernel(
    const float* __restrict__ q, const float* __restrict__ k,
    const float* __restrict__ v, float* __restrict__ o)
{
    constexpr int LDS = 68;
    __shared__ __align__(16) uint32_t ks_ps[64 * LDS];
    __shared__ __align__(16) uint32_t vsT [64 * LDS];
    __shared__ float pmax[2][64];
    __shared__ float psum[2][64];

    int b = blockIdx.z, h = blockIdx.y, qt = blockIdx.x;
    int tid  = threadIdx.x;
    int wid  = tid >> 5, lane = tid & 31;
    int grp  = lane >> 2, tig = lane & 3;
    int wr = wid & 3;
    int wc = wid >> 2;
    const size_t rowstride = (size_t)BATCH * D_MODEL;
    const size_t base = (size_t)b * D_MODEL + h * DH;

    const uint32_t ksps_u = smem_u32(ks_ps);
    const uint32_t vsT_u  = smem_u32(vsT);
    const uint32_t offA = (uint32_t)(((lane & 15) * LDS + ((lane >> 2) & 4)) * 4);
    const uint32_t offB = (uint32_t)((((lane & 7) + ((lane >> 1) & 8)) * LDS + ((lane >> 1) & 4)) * 4);

    uint32_t qf[8][4];
    {
        const float* q0 = q + (size_t)(qt * 64 + wr * 16 + grp) * rowstride + base;
        const float* q1 = q0 + 8 * rowstride;
        #pragma unroll
        for (int s = 0; s < 8; s++) {
            qf[s][0] = __float_as_uint(q0[s * 8 + tig    ] * 0.125f);
            qf[s][1] = __float_as_uint(q1[s * 8 + tig    ] * 0.125f);
            qf[s][2] = __float_as_uint(q0[s * 8 + tig + 4] * 0.125f);
            qf[s][3] = __float_as_uint(q1[s * 8 + tig + 4] * 0.125f);
        }
    }

    float m0 = -1e30f, m1 = -1e30f, l0 = 0.0f, l1 = 0.0f;
    float oacc[4][4];
    #pragma unroll
    for (int i = 0; i < 4; i++)
        #pragma unroll
        for (int j = 0; j < 4; j++) oacc[i][j] = 0.0f;

    int lr = tid >> 2;            // K-load: token row, 64B run shared by 4 lanes
    int lc = (tid & 3) * 16;
    int vtok = tid & 63;          // V-load: 32 consecutive tokens per warp -> conflict-free STS
    int vdh  = (tid >> 6) * 16;
    int row0 = wr * 16 + grp, row1 = row0 + 8;

    for (int tt = 0; tt < 8; tt++) {
        int t0 = tt * 64;
        __syncthreads();
        {
            const float* ksrc = k + (size_t)(t0 + lr) * rowstride + base + lc;
            #pragma unroll
            for (int j = 0; j < 16; j += 4) {
                uint4 u = *(const uint4*)(ksrc + j);           // already tf32
                *(uint4*)(ks_ps + lr * LDS + lc + j) = u;
            }
            const float* vsrc = v + (size_t)(t0 + vtok) * rowstride + base + vdh;
            #pragma unroll
            for (int j = 0; j < 16; j += 4) {
                float4 g = *(const float4*)(vsrc + j);          // already tf32
                vsT[(vdh + j + 0) * LDS + vtok] = __float_as_uint(g.x);
                vsT[(vdh + j + 1) * LDS + vtok] = __float_as_uint(g.y);
                vsT[(vdh + j + 2) * LDS + vtok] = __float_as_uint(g.z);
                vsT[(vdh + j + 3) * LDS + vtok] = __float_as_uint(g.w);
            }
        }
        __syncthreads();

        // GEMM1: S = Q K^T
        float sc[4][4];
        #pragma unroll
        for (int i = 0; i < 4; i++)
            #pragma unroll
            for (int j = 0; j < 4; j++) sc[i][j] = 0.0f;
        {
            uint32_t bU = ksps_u + offB;
            #pragma unroll
            for (int s = 0; s < 8; s++) {
                int kk = s * 8;
                uint32_t bfr[4][2];
                #pragma unroll
                for (int j = 0; j < 2; j++)
                    ldsm_x4(bfr[2*j][0], bfr[2*j][1], bfr[2*j+1][0], bfr[2*j+1][1],
                            bU + (uint32_t)(((wc * 32 + j * 16) * LDS + kk) * 4));
                #pragma unroll
                for (int ni = 0; ni < 4; ni++)
                    mma_tf32(sc[ni], qf[s], bfr[ni][0], bfr[ni][1]);
            }
        }

        float t0m = -1e30f, t1m = -1e30f;
        #pragma unroll
        for (int ni = 0; ni < 4; ni++) {
            t0m = fmaxf(t0m, fmaxf(sc[ni][0], sc[ni][1]));
            t1m = fmaxf(t1m, fmaxf(sc[ni][2], sc[ni][3]));
        }
        t0m = fmaxf(t0m, __shfl_xor_sync(0xffffffffu, t0m, 1));
        t0m = fmaxf(t0m, __shfl_xor_sync(0xffffffffu, t0m, 2));
        t1m = fmaxf(t1m, __shfl_xor_sync(0xffffffffu, t1m, 1));
        t1m = fmaxf(t1m, __shfl_xor_sync(0xffffffffu, t1m, 2));
        if (tig == 0) { pmax[wc][row0] = t0m; pmax[wc][row1] = t1m; }
        __syncthreads();

        float fm0 = fmaxf(pmax[0][row0], pmax[1][row0]);
        float fm1 = fmaxf(pmax[0][row1], pmax[1][row1]);
        float mn0 = fmaxf(m0, fm0), mn1 = fmaxf(m1, fm1);
        float al0 = __expf(m0 - mn0), al1 = __expf(m1 - mn1);
        m0 = mn0; m1 = mn1;

        float rs0 = 0.0f, rs1 = 0.0f;
        #pragma unroll
        for (int ni = 0; ni < 4; ni++) {
            float p00 = __expf(sc[ni][0] - mn0);
            float p01 = __expf(sc[ni][1] - mn0);
            float p10 = __expf(sc[ni][2] - mn1);
            float p11 = __expf(sc[ni][3] - mn1);
            rs0 += p00 + p01; rs1 += p10 + p11;
            int col = wc * 32 + ni * 8 + tig * 2;
            uint2 u0 = { f2tf32(p00), f2tf32(p01) };
            uint2 u1 = { f2tf32(p10), f2tf32(p11) };
            *(uint2*)(ks_ps + row0 * LDS + col) = u0;
            *(uint2*)(ks_ps + row1 * LDS + col) = u1;
        }
        rs0 += __shfl_xor_sync(0xffffffffu, rs0, 1);
        rs0 += __shfl_xor_sync(0xffffffffu, rs0, 2);
        rs1 += __shfl_xor_sync(0xffffffffu, rs1, 1);
        rs1 += __shfl_xor_sync(0xffffffffu, rs1, 2);
        if (tig == 0) { psum[wc][row0] = rs0; psum[wc][row1] = rs1; }
        __syncthreads();

        l0 = l0 * al0 + psum[0][row0] + psum[1][row0];
        l1 = l1 * al1 + psum[0][row1] + psum[1][row1];
        #pragma unroll
        for (int ni = 0; ni < 4; ni++) {
            oacc[ni][0] *= al0; oacc[ni][1] *= al0;
            oacc[ni][2] *= al1; oacc[ni][3] *= al1;
        }

        // GEMM2: O += P V
        {
            uint32_t aU = ksps_u + offA;
            uint32_t bU = vsT_u  + offB;
            #pragma unroll
            for (int s = 0; s < 8; s++) {
                int kk = s * 8;
                uint32_t a[4];
                ldsm_x4(a[0], a[1], a[2], a[3],
                        aU + (uint32_t)(((wr * 16) * LDS + kk) * 4));
                uint32_t bfr[4][2];
                #pragma unroll
                for (int j = 0; j < 2; j++)
                    ldsm_x4(bfr[2*j][0], bfr[2*j][1], bfr[2*j+1][0], bfr[2*j+1][1],
                            bU + (uint32_t)(((wc * 32 + j * 16) * LDS + kk) * 4));
                #pragma unroll
                for (int ni = 0; ni < 4; ni++)
                    mma_tf32(oacc[ni], a, bfr[ni][0], bfr[ni][1]);
            }
        }
    }

    float il0 = 1.0f / l0, il1 = 1.0f / l1;
    int gr0 = qt * 64 + row0, gr1 = qt * 64 + row1;
    #pragma unroll
    for (int ni = 0; ni < 4; ni++) {
        size_t col = base + wc * 32 + ni * 8 + tig * 2;
        float2 o0 = { oacc[ni][0] * il0, oacc[ni][1] * il0 };
        float2 o1 = { oacc[ni][2] * il1, oacc[ni][3] * il1 };
        *(float2*)(o + (size_t)gr0 * rowstride + col) = o0;
        *(float2*)(o + (size_t)gr1 * rowstride + col) = o1;
    }
}

// ---------------- launch ----------------
extern "C" void kernel_launch(void* const* d_in, const int* in_sizes, int n_in,
                              void* d_out, int out_size)
{
    const float* x   = (const float*)d_in[0];
    const float* Wq  = (const float*)d_in[1];
    const float* Wk  = (const float*)d_in[2];
    const float* Wv  = (const float*)d_in[3];
    const float* g1  = (const float*)d_in[4];
    const float* b1  = (const float*)d_in[5];
    const float* g2  = (const float*)d_in[6];
    const float* b2  = (const float*)d_in[7];
    const float* W1  = (const float*)d_in[8];
    const float* bf1 = (const float*)d_in[9];
    const float* W2  = (const float*)d_in[10];
    const float* bf2 = (const float*)d_in[11];
    float* out = (float*)d_out;

    float *xn, *qb, *kb, *vb, *att, *xt, *h1;
    float *wqkv, *w1, *w2;
    cudaGetSymbolAddress((void**)&xn,   g_xn);
    cudaGetSymbolAddress((void**)&qb,   g_q);
    cudaGetSymbolAddress((void**)&kb,   g_k);
    cudaGetSymbolAddress((void**)&vb,   g_v);
    cudaGetSymbolAddress((void**)&att,  g_att);
    cudaGetSymbolAddress((void**)&xt,   g_xt);
    cudaGetSymbolAddress((void**)&h1,   g_h1);
    cudaGetSymbolAddress((void**)&wqkv, g_wqkv);
    cudaGetSymbolAddress((void**)&w1,   g_w1);
    cudaGetSymbolAddress((void**)&w2,   g_w2);

    cudaFuncSetAttribute(tc_gemm<1>,  cudaFuncAttributeMaxDynamicSharedMemorySize, GEMM_SMEM);
    cudaFuncSetAttribute(tc_gemm<2>,  cudaFuncAttributeMaxDynamicSharedMemorySize, GEMM_SMEM);
    cudaFuncSetAttribute(tc_gemm_qkv, cudaFuncAttributeMaxDynamicSharedMemorySize, GEMM_SMEM);

    round_w_all<<<5 * (WELEM / 4 / 256), 256>>>(Wq, Wk, Wv, W1, W2, wqkv, w1, w2);

    dim3 gg(D_MODEL / 128, ROWS / 128);      // (4, 256)
    dim3 gq(3 * D_MODEL / 128, ROWS / 128);  // (12, 256)

    ln_kernel<<<ROWS, 128>>>(x, nullptr, g1, b1, xn);
    tc_gemm_qkv<<<gq, 256, GEMM_SMEM>>>(xn, wqkv, qb, kb, vb);
    attn_tc_kernel<<<dim3(S_LEN / 64, NHEAD, BATCH), 256>>>(qb, kb, vb, att);
    ln_kernel<<<ROWS, 128>>>(xn, att, g2, b2, xt);
    tc_gemm<1><<<gg, 256, GEMM_SMEM>>>(xt, w1, bf1, nullptr, h1);
    tc_gemm<2><<<gg, 256, GEMM_SMEM>>>(h1, w2, bf2, xt, out);
}

// round 15
// speedup vs baseline: 1.2323x; 1.2323x over previous
#include <cuda_runtime.h>
#include <cuda_bf16.h>
#include <cstdint>
#include <cstddef>

#define D_MODEL 512
#define S_LEN   512
#define BATCH   64
#define NHEAD   8
#define DH      64
#define ROWS    (S_LEN * BATCH)          // 32768
#define NELEM   ((size_t)ROWS * D_MODEL) // 16,777,216
#define WELEM   (D_MODEL * D_MODEL)      // 262,144

// ---------------- scratch (no allocations allowed) ----------------
__device__ float g_xn[NELEM];
__device__ float g_q [NELEM];
__device__ float g_k [NELEM];
__device__ float g_v [NELEM];
__device__ float g_att[NELEM];
__device__ float g_xt[NELEM];
__device__ float g_h1[NELEM];
__device__ float g_wqkv[3 * WELEM];
__device__ float g_w1[WELEM];
__device__ float g_w2[WELEM];

// ================= tf32 warp-mma helpers =================
__device__ __forceinline__ uint32_t f2tf32(float f) {
    uint32_t u;
    asm("cvt.rna.tf32.f32 %0, %1;" : "=r"(u) : "f"(f));
    return u;
}
__device__ __forceinline__ float tf32f(float f) {
    return __uint_as_float(f2tf32(f));
}
__device__ __forceinline__ void mma_tf32(float* c, const uint32_t* a, uint32_t b0, uint32_t b1) {
    asm volatile(
        "mma.sync.aligned.m16n8k8.row.col.f32.tf32.tf32.f32 "
        "{%0,%1,%2,%3}, {%4,%5,%6,%7}, {%8,%9}, {%0,%1,%2,%3};"
        : "+f"(c[0]), "+f"(c[1]), "+f"(c[2]), "+f"(c[3])
        : "r"(a[0]), "r"(a[1]), "r"(a[2]), "r"(a[3]), "r"(b0), "r"(b1));
}
__device__ __forceinline__ void ldsm_x4(uint32_t& r0, uint32_t& r1, uint32_t& r2, uint32_t& r3,
                                        uint32_t addr) {
    asm volatile("ldmatrix.sync.aligned.m8n8.x4.shared.b16 {%0,%1,%2,%3}, [%4];"
                 : "=r"(r0), "=r"(r1), "=r"(r2), "=r"(r3) : "r"(addr));
}
__device__ __forceinline__ uint32_t smem_u32(const void* p) {
    uint32_t a;
    asm("{ .reg .u64 t; cvta.to.shared.u64 t, %1; cvt.u32.u64 %0, t; }" : "=r"(a) : "l"(p));
    return a;
}
__device__ __forceinline__ void cp_async16(uint32_t saddr, const void* g) {
    asm volatile("cp.async.cg.shared.global [%0], [%1], 16;" :: "r"(saddr), "l"(g));
}
#define CP_COMMIT() asm volatile("cp.async.commit_group;" ::: "memory")
#define CP_WAIT0()  asm volatile("cp.async.wait_group 0;" ::: "memory")

// ---------------- fused weight pre-rounding to tf32 (rna) ----------------
__global__ void __launch_bounds__(256) round_w_all(
    const float* __restrict__ Wq, const float* __restrict__ Wk, const float* __restrict__ Wv,
    const float* __restrict__ W1, const float* __restrict__ W2,
    float* __restrict__ wqkv, float* __restrict__ w1, float* __restrict__ w2)
{
    int slot = blockIdx.x * 256 + threadIdx.x;
    int region = slot / (WELEM / 4);
    int off    = slot % (WELEM / 4);
    const float* src;
    float* dst;
    switch (region) {
        case 0: src = Wq; dst = wqkv;              break;
        case 1: src = Wk; dst = wqkv + WELEM;      break;
        case 2: src = Wv; dst = wqkv + 2 * WELEM;  break;
        case 3: src = W1; dst = w1;                break;
        default: src = W2; dst = w2;               break;
    }
    float4 f = ((const float4*)src)[off];
    float4 r = { tf32f(f.x), tf32f(f.y), tf32f(f.z), tf32f(f.w) };
    ((float4*)dst)[off] = r;
}

// ---------------- LayerNorm (optionally fused residual add), tf32-rounded output ----------------
__global__ void __launch_bounds__(128) ln_kernel(
    const float* __restrict__ x, const float* __restrict__ res,
    const float* __restrict__ gamma, const float* __restrict__ beta,
    float* __restrict__ out)
{
    int row = blockIdx.x;
    int t = threadIdx.x;
    const float4* xr = (const float4*)(x + (size_t)row * D_MODEL);
    float4 v = xr[t];
    if (res) {
        const float4* rr = (const float4*)(res + (size_t)row * D_MODEL);
        float4 r = rr[t];
        v.x += r.x; v.y += r.y; v.z += r.z; v.w += r.w;
    }
    float s  = v.x + v.y + v.z + v.w;
    float sq = v.x*v.x + v.y*v.y + v.z*v.z + v.w*v.w;
    #pragma unroll
    for (int o = 16; o > 0; o >>= 1) {
        s  += __shfl_xor_sync(0xffffffffu, s,  o);
        sq += __shfl_xor_sync(0xffffffffu, sq, o);
    }
    __shared__ float ss[4], ssq[4];
    int w = t >> 5;
    if ((t & 31) == 0) { ss[w] = s; ssq[w] = sq; }
    __syncthreads();
    s  = ss[0] + ss[1] + ss[2] + ss[3];
    sq = ssq[0] + ssq[1] + ssq[2] + ssq[3];
    const float invD = 1.0f / D_MODEL;
    float mu   = s * invD;
    float var  = sq * invD - mu * mu;
    float rstd = rsqrtf(var + 1e-5f);
    float4 g = ((const float4*)gamma)[t];
    float4 b = ((const float4*)beta )[t];
    float4 o;
    o.x = tf32f((v.x - mu) * rstd * g.x + b.x);
    o.y = tf32f((v.y - mu) * rstd * g.y + b.y);
    o.z = tf32f((v.z - mu) * rstd * g.z + b.z);
    o.w = tf32f((v.w - mu) * rstd * g.w + b.w);
    ((float4*)(out + (size_t)row * D_MODEL))[t] = o;
}

// ============ shared GEMM config ============
#define GEMM_LDS   36
#define GEMM_STAGE (128 * GEMM_LDS)
#define GEMM_SMEM  (4 * GEMM_STAGE * 4)   // 73728 B

// ============ tf32 GEMM: C = A*W^T (+bias)(+relu)(+res), N=512 ============
template<int MODE>
__global__ void __launch_bounds__(256) tc_gemm(
    const float* __restrict__ A, const float* __restrict__ W,
    const float* __restrict__ bias, const float* __restrict__ res,
    float* __restrict__ C)
{
    constexpr int K = 512, N = 512, BK = 32, LDS = GEMM_LDS;
    extern __shared__ uint32_t dyn[];

    int tid  = threadIdx.x;
    int wid  = tid >> 5, lane = tid & 31;
    int grp  = lane >> 2, tig = lane & 3;
    int m0 = blockIdx.y * 128, n0 = blockIdx.x * 128;
    int wm = wid & 3;
    int wn = wid >> 2;

    int lrow[4], lcol[4];
    #pragma unroll
    for (int it = 0; it < 4; it++) {
        int slot = tid + it * 256;
        lrow[it] = slot >> 3;
        lcol[it] = (slot & 7) * 4;
    }
    uint32_t sA_u[2] = { smem_u32(dyn),                  smem_u32(dyn + GEMM_STAGE)     };
    uint32_t sB_u[2] = { smem_u32(dyn + 2 * GEMM_STAGE), smem_u32(dyn + 3 * GEMM_STAGE) };

    const uint32_t offA = (uint32_t)(((lane & 15) * LDS + ((lane >> 2) & 4)) * 4);
    const uint32_t offB = (uint32_t)((((lane & 7) + ((lane >> 1) & 8)) * LDS + ((lane >> 1) & 4)) * 4);

    float acc[2][8][4];
    #pragma unroll
    for (int i = 0; i < 2; i++)
        #pragma unroll
        for (int j = 0; j < 8; j++)
            #pragma unroll
            for (int q = 0; q < 4; q++) acc[i][j][q] = 0.0f;

    #pragma unroll
    for (int it = 0; it < 4; it++) {
        cp_async16(sA_u[0] + (lrow[it] * LDS + lcol[it]) * 4,
                   A + (size_t)(m0 + lrow[it]) * K + lcol[it]);
        cp_async16(sB_u[0] + (lrow[it] * LDS + lcol[it]) * 4,
                   W + (size_t)(n0 + lrow[it]) * K + lcol[it]);
    }
    CP_COMMIT();

    for (int chunk = 0; chunk < 16; chunk++) {
        int buf = chunk & 1;
        CP_WAIT0();
        __syncthreads();

        if (chunk < 15) {
            int k0 = (chunk + 1) * BK;
            int nbuf = buf ^ 1;
            #pragma unroll
            for (int it = 0; it < 4; it++) {
                cp_async16(sA_u[nbuf] + (lrow[it] * LDS + lcol[it]) * 4,
                           A + (size_t)(m0 + lrow[it]) * K + k0 + lcol[it]);
                cp_async16(sB_u[nbuf] + (lrow[it] * LDS + lcol[it]) * 4,
                           W + (size_t)(n0 + lrow[it]) * K + k0 + lcol[it]);
            }
            CP_COMMIT();
        }

        uint32_t aU = sA_u[buf] + offA;
        uint32_t bU = sB_u[buf] + offB;
        #pragma unroll
        for (int ks = 0; ks < 4; ks++) {
            int kk = ks * 8;
            uint32_t a[2][4];
            #pragma unroll
            for (int mi = 0; mi < 2; mi++)
                ldsm_x4(a[mi][0], a[mi][1], a[mi][2], a[mi][3],
                        aU + (uint32_t)(((wm * 32 + mi * 16) * LDS + kk) * 4));
            uint32_t b[8][2];
            #pragma unroll
            for (int j = 0; j < 4; j++)
                ldsm_x4(b[2*j][0], b[2*j][1], b[2*j+1][0], b[2*j+1][1],
                        bU + (uint32_t)(((wn * 64 + j * 16) * LDS + kk) * 4));
            #pragma unroll
            for (int mi = 0; mi < 2; mi++)
                #pragma unroll
                for (int ni = 0; ni < 8; ni++)
                    mma_tf32(acc[mi][ni], a[mi], b[ni][0], b[ni][1]);
        }
    }

    #pragma unroll
    for (int mi = 0; mi < 2; mi++) {
        #pragma unroll
        for (int h = 0; h < 2; h++) {
            int m = m0 + wm * 32 + mi * 16 + grp + h * 8;
            #pragma unroll
            for (int ni = 0; ni < 8; ni++) {
                int n = n0 + wn * 64 + ni * 8 + tig * 2;
                float2 o;
                o.x = acc[mi][ni][h * 2 + 0];
                o.y = acc[mi][ni][h * 2 + 1];
                if (MODE >= 1) {
                    float2 bb = *(const float2*)(bias + n);
                    o.x += bb.x; o.y += bb.y;
                }
                if (MODE == 1) {
                    o.x = fmaxf(o.x, 0.f); o.y = fmaxf(o.y, 0.f);
                }
                if (MODE == 2) {
                    float2 rr = *(const float2*)(res + (size_t)m * N + n);
                    o.x += rr.x; o.y += rr.y;
                }
                if (MODE != 2) { o.x = tf32f(o.x); o.y = tf32f(o.y); }
                *(float2*)(C + (size_t)m * N + n) = o;
            }
        }
    }
}

// ============ fused QKV GEMM: N=1536 (Wq|Wk|Wv stacked) ============
__global__ void __launch_bounds__(256) tc_gemm_qkv(
    const float* __restrict__ A, const float* __restrict__ W,
    float* __restrict__ Cq, float* __restrict__ Ck, float* __restrict__ Cv)
{
    constexpr int K = 512, LDS = GEMM_LDS, BK = 32;
    extern __shared__ uint32_t dyn[];

    int tid  = threadIdx.x;
    int wid  = tid >> 5, lane = tid & 31;
    int grp  = lane >> 2, tig = lane & 3;
    int m0 = blockIdx.y * 128, n0 = blockIdx.x * 128;
    int wm = wid & 3;
    int wn = wid >> 2;

    int lrow[4], lcol[4];
    #pragma unroll
    for (int it = 0; it < 4; it++) {
        int slot = tid + it * 256;
        lrow[it] = slot >> 3;
        lcol[it] = (slot & 7) * 4;
    }
    uint32_t sA_u[2] = { smem_u32(dyn),                  smem_u32(dyn + GEMM_STAGE)     };
    uint32_t sB_u[2] = { smem_u32(dyn + 2 * GEMM_STAGE), smem_u32(dyn + 3 * GEMM_STAGE) };

    const uint32_t offA = (uint32_t)(((lane & 15) * LDS + ((lane >> 2) & 4)) * 4);
    const uint32_t offB = (uint32_t)((((lane & 7) + ((lane >> 1) & 8)) * LDS + ((lane >> 1) & 4)) * 4);

    float acc[2][8][4];
    #pragma unroll
    for (int i = 0; i < 2; i++)
        #pragma unroll
        for (int j = 0; j < 8; j++)
            #pragma unroll
            for (int q = 0; q < 4; q++) acc[i][j][q] = 0.0f;

    #pragma unroll
    for (int it = 0; it < 4; it++) {
        cp_async16(sA_u[0] + (lrow[it] * LDS + lcol[it]) * 4,
                   A + (size_t)(m0 + lrow[it]) * K + lcol[it]);
        cp_async16(sB_u[0] + (lrow[it] * LDS + lcol[it]) * 4,
                   W + (size_t)(n0 + lrow[it]) * K + lcol[it]);
    }
    CP_COMMIT();

    for (int chunk = 0; chunk < 16; chunk++) {
        int buf = chunk & 1;
        CP_WAIT0();
        __syncthreads();

        if (chunk < 15) {
            int k0 = (chunk + 1) * BK;
            int nbuf = buf ^ 1;
            #pragma unroll
            for (int it = 0; it < 4; it++) {
                cp_async16(sA_u[nbuf] + (lrow[it] * LDS + lcol[it]) * 4,
                           A + (size_t)(m0 + lrow[it]) * K + k0 + lcol[it]);
                cp_async16(sB_u[nbuf] + (lrow[it] * LDS + lcol[it]) * 4,
                           W + (size_t)(n0 + lrow[it]) * K + k0 + lcol[it]);
            }
            CP_COMMIT();
        }

        uint32_t aU = sA_u[buf] + offA;
        uint32_t bU = sB_u[buf] + offB;
        #pragma unroll
        for (int ks = 0; ks < 4; ks++) {
            int kk = ks * 8;
            uint32_t a[2][4];
            #pragma unroll
            for (int mi = 0; mi < 2; mi++)
                ldsm_x4(a[mi][0], a[mi][1], a[mi][2], a[mi][3],
                        aU + (uint32_t)(((wm * 32 + mi * 16) * LDS + kk) * 4));
            uint32_t b[8][2];
            #pragma unroll
            for (int j = 0; j < 4; j++)
                ldsm_x4(b[2*j][0], b[2*j][1], b[2*j+1][0], b[2*j+1][1],
                        bU + (uint32_t)(((wn * 64 + j * 16) * LDS + kk) * 4));
            #pragma unroll
            for (int mi = 0; mi < 2; mi++)
                #pragma unroll
                for (int ni = 0; ni < 8; ni++)
                    mma_tf32(acc[mi][ni], a[mi], b[ni][0], b[ni][1]);
        }
    }

    float* C = (n0 < 512) ? Cq : (n0 < 1024 ? Ck : Cv);
    int nb = n0 & 511;
    #pragma unroll
    for (int mi = 0; mi < 2; mi++) {
        #pragma unroll
        for (int h = 0; h < 2; h++) {
            int m = m0 + wm * 32 + mi * 16 + grp + h * 8;
            #pragma unroll
            for (int ni = 0; ni < 8; ni++) {
                int n = nb + wn * 64 + ni * 8 + tig * 2;
                float2 o;
                o.x = tf32f(acc[mi][ni][h * 2 + 0]);
                o.y = tf32f(acc[mi][ni][h * 2 + 1]);
                *(float2*)(C + (size_t)m * 512 + n) = o;
            }
        }
    }
}

// ============ tf32 flash attention: 128 Q rows/CTA, full-width warps, register P ============
// 8 warps x (16 rows x all 64 KV cols). Softmax fully warp-local; P permuted
// accumulator->A-frag via quad shuffles, never touches smem.
__global__ void __launch_bounds__(256, 2) attn_tc_kernel(
    const float* __restrict__ q, const float* __restrict__ k,
    const float* __restrict__ v, float* __restrict__ o)
{
    constexpr int LDS = 68;
    __shared__ __align__(16) uint32_t ks [64 * LDS];
    __shared__ __align__(16) uint32_t vsT[64 * LDS];

    int b = blockIdx.z, h = blockIdx.y, qt = blockIdx.x;
    int tid  = threadIdx.x;
    int wid  = tid >> 5, lane = tid & 31;
    int grp  = lane >> 2, tig = lane & 3;
    const size_t rowstride = (size_t)BATCH * D_MODEL;
    const size_t base = (size_t)b * D_MODEL + h * DH;

    const uint32_t ks_u  = smem_u32(ks);
    const uint32_t vsT_u = smem_u32(vsT);
    const uint32_t offB = (uint32_t)((((lane & 7) + ((lane >> 1) & 8)) * LDS + ((lane >> 1) & 4)) * 4);

    // permutation lanes: col c of an 8-col group lives at quad-lane c>>1, element c&1
    const int srcA = (lane & ~3) | (tig >> 1);
    const int srcB = srcA + 2;
    const bool oddc = (tig & 1);

    // Q fragments (16 rows x 64 cols), already tf32; *0.125 exact
    uint32_t qf[8][4];
    {
        const float* q0 = q + (size_t)(qt * 128 + wid * 16 + grp) * rowstride + base;
        const float* q1 = q0 + 8 * rowstride;
        #pragma unroll
        for (int s = 0; s < 8; s++) {
            qf[s][0] = __float_as_uint(q0[s * 8 + tig    ] * 0.125f);
            qf[s][1] = __float_as_uint(q1[s * 8 + tig    ] * 0.125f);
            qf[s][2] = __float_as_uint(q0[s * 8 + tig + 4] * 0.125f);
            qf[s][3] = __float_as_uint(q1[s * 8 + tig + 4] * 0.125f);
        }
    }

    float m0 = -1e30f, m1 = -1e30f, l0 = 0.0f, l1 = 0.0f;
    float oacc[8][4];
    #pragma unroll
    for (int i = 0; i < 8; i++)
        #pragma unroll
        for (int j = 0; j < 4; j++) oacc[i][j] = 0.0f;

    int lr = tid >> 2;
    int lc = (tid & 3) * 16;

    for (int tt = 0; tt < 8; tt++) {
        int t0 = tt * 64;
        __syncthreads();
        {
            const float* ksrc = k + (size_t)(t0 + lr) * rowstride + base + lc;
            const float* vsrc = v + (size_t)(t0 + lr) * rowstride + base + lc;
            #pragma unroll
            for (int j = 0; j < 16; j += 4) {
                uint4 u = *(const uint4*)(ksrc + j);            // already tf32
                *(uint4*)(ks + lr * LDS + lc + j) = u;
                float4 g = *(const float4*)(vsrc + j);           // already tf32
                vsT[(lc + j + 0) * LDS + lr] = __float_as_uint(g.x);
                vsT[(lc + j + 1) * LDS + lr] = __float_as_uint(g.y);
                vsT[(lc + j + 2) * LDS + lr] = __float_as_uint(g.z);
                vsT[(lc + j + 3) * LDS + lr] = __float_as_uint(g.w);
            }
        }
        __syncthreads();

        // GEMM1: S(16x64) = Q K^T
        float sc[8][4];
        #pragma unroll
        for (int i = 0; i < 8; i++)
            #pragma unroll
            for (int j = 0; j < 4; j++) sc[i][j] = 0.0f;
        {
            uint32_t bU = ks_u + offB;
            #pragma unroll
            for (int s = 0; s < 8; s++) {
                int kk = s * 8;
                uint32_t bfr[8][2];
                #pragma unroll
                for (int j = 0; j < 4; j++)
                    ldsm_x4(bfr[2*j][0], bfr[2*j][1], bfr[2*j+1][0], bfr[2*j+1][1],
                            bU + (uint32_t)(((j * 16) * LDS + kk) * 4));
                #pragma unroll
                for (int ni = 0; ni < 8; ni++)
                    mma_tf32(sc[ni], qf[s], bfr[ni][0], bfr[ni][1]);
            }
        }

        // warp-local softmax (rows grp / grp+8 fully owned by this warp's quad)
        float t0m = -1e30f, t1m = -1e30f;
        #pragma unroll
        for (int ni = 0; ni < 8; ni++) {
            t0m = fmaxf(t0m, fmaxf(sc[ni][0], sc[ni][1]));
            t1m = fmaxf(t1m, fmaxf(sc[ni][2], sc[ni][3]));
        }
        t0m = fmaxf(t0m, __shfl_xor_sync(0xffffffffu, t0m, 1));
        t0m = fmaxf(t0m, __shfl_xor_sync(0xffffffffu, t0m, 2));
        t1m = fmaxf(t1m, __shfl_xor_sync(0xffffffffu, t1m, 1));
        t1m = fmaxf(t1m, __shfl_xor_sync(0xffffffffu, t1m, 2));

        float mn0 = fmaxf(m0, t0m), mn1 = fmaxf(m1, t1m);
        float al0 = __expf(m0 - mn0), al1 = __expf(m1 - mn1);
        m0 = mn0; m1 = mn1;

        float rs0 = 0.0f, rs1 = 0.0f;
        #pragma unroll
        for (int ni = 0; ni < 8; ni++) {
            sc[ni][0] = __expf(sc[ni][0] - mn0);
            sc[ni][1] = __expf(sc[ni][1] - mn0);
            sc[ni][2] = __expf(sc[ni][2] - mn1);
            sc[ni][3] = __expf(sc[ni][3] - mn1);
            rs0 += sc[ni][0] + sc[ni][1];
            rs1 += sc[ni][2] + sc[ni][3];
        }
        rs0 += __shfl_xor_sync(0xffffffffu, rs0, 1);
        rs0 += __shfl_xor_sync(0xffffffffu, rs0, 2);
        rs1 += __shfl_xor_sync(0xffffffffu, rs1, 1);
        rs1 += __shfl_xor_sync(0xffffffffu, rs1, 2);
        l0 = l0 * al0 + rs0;
        l1 = l1 * al1 + rs1;
        #pragma unroll
        for (int ni = 0; ni < 8; ni++) {
            oacc[ni][0] *= al0; oacc[ni][1] *= al0;
            oacc[ni][2] *= al1; oacc[ni][3] *= al1;
        }

        // GEMM2: O += P V, P permuted from accumulator layout on the fly
        {
            uint32_t bU = vsT_u + offB;
            #pragma unroll
            for (int s = 0; s < 8; s++) {
                int kk = s * 8;
                // accumulator cols {2*tig, 2*tig+1} -> A-frag cols {tig, tig+4}
                float e0 = __shfl_sync(0xffffffffu, sc[s][0], srcA);
                float e1 = __shfl_sync(0xffffffffu, sc[s][1], srcA);
                float f0 = __shfl_sync(0xffffffffu, sc[s][2], srcA);
                float f1 = __shfl_sync(0xffffffffu, sc[s][3], srcA);
                float g0 = __shfl_sync(0xffffffffu, sc[s][0], srcB);
                float g1 = __shfl_sync(0xffffffffu, sc[s][1], srcB);
                float h0 = __shfl_sync(0xffffffffu, sc[s][2], srcB);
                float h1 = __shfl_sync(0xffffffffu, sc[s][3], srcB);
                uint32_t a[4];
                a[0] = f2tf32(oddc ? e1 : e0);
                a[1] = f2tf32(oddc ? f1 : f0);
                a[2] = f2tf32(oddc ? g1 : g0);
                a[3] = f2tf32(oddc ? h1 : h0);
                uint32_t bfr[8][2];
                #pragma unroll
                for (int j = 0; j < 4; j++)
                    ldsm_x4(bfr[2*j][0], bfr[2*j][1], bfr[2*j+1][0], bfr[2*j+1][1],
                            bU + (uint32_t)(((j * 16) * LDS + kk) * 4));
                #pragma unroll
                for (int ni = 0; ni < 8; ni++)
                    mma_tf32(oacc[ni], a, bfr[ni][0], bfr[ni][1]);
            }
        }
    }

    // finalize
    float il0 = 1.0f / l0, il1 = 1.0f / l1;
    int gr0 = qt * 128 + wid * 16 + grp, gr1 = gr0 + 8;
    #pragma unroll
    for (int ni = 0; ni < 8; ni++) {
        size_t col = base + ni * 8 + tig * 2;
        float2 o0 = { oacc[ni][0] * il0, oacc[ni][1] * il0 };
        float2 o1 = { oacc[ni][2] * il1, oacc[ni][3] * il1 };
        *(float2*)(o + (size_t)gr0 * rowstride + col) = o0;
        *(float2*)(o + (size_t)gr1 * rowstride + col) = o1;
    }
}

// ---------------- launch ----------------
extern "C" void kernel_launch(void* const* d_in, const int* in_sizes, int n_in,
                              void* d_out, int out_size)
{
    const float* x   = (const float*)d_in[0];
    const float* Wq  = (const float*)d_in[1];
    const float* Wk  = (const float*)d_in[2];
    const float* Wv  = (const float*)d_in[3];
    const float* g1  = (const float*)d_in[4];
    const float* b1  = (const float*)d_in[5];
    const float* g2  = (const float*)d_in[6];
    const float* b2  = (const float*)d_in[7];
    const float* W1  = (const float*)d_in[8];
    const float* bf1 = (const float*)d_in[9];
    const float* W2  = (const float*)d_in[10];
    const float* bf2 = (const float*)d_in[11];
    float* out = (float*)d_out;

    float *xn, *qb, *kb, *vb, *att, *xt, *h1;
    float *wqkv, *w1, *w2;
    cudaGetSymbolAddress((void**)&xn,   g_xn);
    cudaGetSymbolAddress((void**)&qb,   g_q);
    cudaGetSymbolAddress((void**)&kb,   g_k);
    cudaGetSymbolAddress((void**)&vb,   g_v);
    cudaGetSymbolAddress((void**)&att,  g_att);
    cudaGetSymbolAddress((void**)&xt,   g_xt);
    cudaGetSymbolAddress((void**)&h1,   g_h1);
    cudaGetSymbolAddress((void**)&wqkv, g_wqkv);
    cudaGetSymbolAddress((void**)&w1,   g_w1);
    cudaGetSymbolAddress((void**)&w2,   g_w2);

    cudaFuncSetAttribute(tc_gemm<1>,  cudaFuncAttributeMaxDynamicSharedMemorySize, GEMM_SMEM);
    cudaFuncSetAttribute(tc_gemm<2>,  cudaFuncAttributeMaxDynamicSharedMemorySize, GEMM_SMEM);
    cudaFuncSetAttribute(tc_gemm_qkv, cudaFuncAttributeMaxDynamicSharedMemorySize, GEMM_SMEM);

    round_w_all<<<5 * (WELEM / 4 / 256), 256>>>(Wq, Wk, Wv, W1, W2, wqkv, w1, w2);

    dim3 gg(D_MODEL / 128, ROWS / 128);      // (4, 256)
    dim3 gq(3 * D_MODEL / 128, ROWS / 128);  // (12, 256)

    ln_kernel<<<ROWS, 128>>>(x, nullptr, g1, b1, xn);
    tc_gemm_qkv<<<gq, 256, GEMM_SMEM>>>(xn, wqkv, qb, kb, vb);
    attn_tc_kernel<<<dim3(S_LEN / 128, NHEAD, BATCH), 256>>>(qb, kb, vb, att);
    ln_kernel<<<ROWS, 128>>>(xn, att, g2, b2, xt);
    tc_gemm<1><<<gg, 256, GEMM_SMEM>>>(xt, w1, bf1, nullptr, h1);
    tc_gemm<2><<<gg, 256, GEMM_SMEM>>>(h1, w2, bf2, xt, out);
}